// round 1
// baseline (speedup 1.0000x reference)
#include <cuda_runtime.h>
#include <cuda_bf16.h>
#include <math.h>
#include <limits.h>

// ---------------- problem constants ----------------
#define KSEL   50          // NUM_POINTS
#define FDIM   90          // feature dim
#define PCAP   4096        // PMAX
#define RMAX   256
#define NMAX   600000
#define SMAX   16          // max split-K slices

// ---------------- device scratch (no allocs allowed) ----------------
__device__ int    g_counts[RMAX];
__device__ int    g_offsets[RMAX];
__device__ int    g_cursors[RMAX];
__device__ float4 g_packed[NMAX];
__device__ int    g_sel[RMAX * KSEL];
__device__ float  g_feat[RMAX * KSEL * FDIM];       // [R, 4500]
__device__ float  g_part[SMAX * RMAX * 512];        // split-K partials
__device__ float  g_hA[RMAX * 512];
__device__ float  g_hB[RMAX * 512];

// ---------------- preprocessing ----------------
__global__ void zero_counts_kernel(int R) {
    int t = threadIdx.x;
    if (t < R) { g_counts[t] = 0; }
}

__global__ void hist_kernel(const int* __restrict__ idx, int Np) {
    int i = blockIdx.x * blockDim.x + threadIdx.x;
    if (i < Np) atomicAdd(&g_counts[idx[i]], 1);
}

// single block, blockDim == R (power of two, R=256)
__global__ void scan_kernel(int R) {
    __shared__ int tmp[1024];
    int t = threadIdx.x;
    int v = (t < R) ? g_counts[t] : 0;
    tmp[t] = v;
    __syncthreads();
    for (int o = 1; o < blockDim.x; o <<= 1) {
        int x = (t >= o) ? tmp[t - o] : 0;
        __syncthreads();
        tmp[t] += x;
        __syncthreads();
    }
    if (t < R) {
        int excl = tmp[t] - v;
        g_offsets[t] = excl;
        g_cursors[t] = excl;
    }
}

__global__ void scatter_kernel(const int* __restrict__ idx,
                               const float* __restrict__ coords, int Np) {
    int i = blockIdx.x * blockDim.x + threadIdx.x;
    if (i < Np) {
        int r = idx[i];
        int slot = atomicAdd(&g_cursors[r], 1);
        float4 p;
        p.x = coords[3 * i + 0];
        p.y = coords[3 * i + 1];
        p.z = coords[3 * i + 2];
        p.w = __int_as_float(i);
        if (slot < NMAX) g_packed[slot] = p;
    }
}

// ---------------- FPS: one block per ROI ----------------
// dynamic smem: sx,sy,sz,sd (float[PCAP] each) + sid (int[PCAP]) = 80KB
__global__ void fps_kernel(int K) {
    extern __shared__ float sm[];
    float* sx  = sm;
    float* sy  = sx + PCAP;
    float* sz  = sy + PCAP;
    float* sd  = sz + PCAP;
    int*   sid = (int*)(sd + PCAP);

    __shared__ float rv[8];
    __shared__ int   rid[8], rpos[8];
    __shared__ float lastx, lasty, lastz;

    int r = blockIdx.x;
    int P = g_counts[r];
    if (P > PCAP) P = PCAP;
    if (P == 0) return;
    int off = g_offsets[r];
    int tid = threadIdx.x;
    int nw  = blockDim.x >> 5;

    for (int j = tid; j < P; j += blockDim.x) {
        float4 p = g_packed[off + j];
        sx[j] = p.x; sy[j] = p.y; sz[j] = p.z;
        sid[j] = __float_as_int(p.w);
        sd[j] = 1e10f;
    }
    __syncthreads();

    // first selection: minimum global id (== reference's stable position 0)
    {
        int bi = INT_MAX, bp = -1;
        for (int j = tid; j < P; j += blockDim.x) {
            int id = sid[j];
            if (id < bi) { bi = id; bp = j; }
        }
        for (int o = 16; o > 0; o >>= 1) {
            int oi = __shfl_down_sync(~0u, bi, o);
            int op = __shfl_down_sync(~0u, bp, o);
            if (oi < bi) { bi = oi; bp = op; }
        }
        if ((tid & 31) == 0) { rid[tid >> 5] = bi; rpos[tid >> 5] = bp; }
        __syncthreads();
        if (tid == 0) {
            int BI = rid[0], BP = rpos[0];
            for (int w = 1; w < nw; w++)
                if (rid[w] < BI) { BI = rid[w]; BP = rpos[w]; }
            g_sel[r * K + 0] = BI;
            lastx = sx[BP]; lasty = sy[BP]; lastz = sz[BP];
        }
        __syncthreads();
    }

    for (int it = 1; it < K; it++) {
        float lx = lastx, ly = lasty, lz = lastz;
        float bv = -2.0f; int bi = INT_MAX; int bp = -1;
        for (int j = tid; j < P; j += blockDim.x) {
            float dx = sx[j] - lx, dy = sy[j] - ly, dz = sz[j] - lz;
            float d  = dx * dx + dy * dy + dz * dz;
            float nd = fminf(sd[j], d);
            sd[j] = nd;
            int id = sid[j];
            if (nd > bv || (nd == bv && id < bi)) { bv = nd; bi = id; bp = j; }
        }
        for (int o = 16; o > 0; o >>= 1) {
            float ov = __shfl_down_sync(~0u, bv, o);
            int   oi = __shfl_down_sync(~0u, bi, o);
            int   op = __shfl_down_sync(~0u, bp, o);
            if (ov > bv || (ov == bv && oi < bi)) { bv = ov; bi = oi; bp = op; }
        }
        if ((tid & 31) == 0) { rv[tid >> 5] = bv; rid[tid >> 5] = bi; rpos[tid >> 5] = bp; }
        __syncthreads();
        if (tid == 0) {
            float BV = rv[0]; int BI = rid[0], BP = rpos[0];
            for (int w = 1; w < nw; w++) {
                if (rv[w] > BV || (rv[w] == BV && rid[w] < BI)) {
                    BV = rv[w]; BI = rid[w]; BP = rpos[w];
                }
            }
            g_sel[r * K + it] = BI;
            lastx = sx[BP]; lasty = sy[BP]; lastz = sz[BP];
        }
        __syncthreads();
    }
}

// ---------------- feature gather ----------------
__global__ void gather_kernel(const float* __restrict__ feats, int K, int F) {
    int r = blockIdx.x;
    int tot = K * F;
    bool zero = (g_counts[r] == 0);
    for (int e = threadIdx.x; e < tot; e += blockDim.x) {
        float v = 0.0f;
        if (!zero) {
            int k = e / F;
            int f = e - k * F;
            v = feats[(size_t)g_sel[r * K + k] * F + f];
        }
        g_feat[(size_t)r * tot + e] = v;
    }
}

// ---------------- split-K SGEMM: 64x64 tile, 4x4 microtile, 256 threads ----------------
#define KT 16
__global__ void gemm_splitk_kernel(const float* __restrict__ A,
                                   const float* __restrict__ B,
                                   int M, int N, int K, int chunk) {
    __shared__ float As[64][KT + 1];
    __shared__ float Bs[KT][64 + 1];
    int s  = blockIdx.z;
    int k0 = s * chunk;
    int k1 = k0 + chunk; if (k1 > K) k1 = K;
    int m0 = blockIdx.y * 64, n0 = blockIdx.x * 64;
    int tid = threadIdx.x;
    int tn = tid & 15, tm = tid >> 4;

    float acc[4][4];
#pragma unroll
    for (int i = 0; i < 4; i++)
#pragma unroll
        for (int j = 0; j < 4; j++) acc[i][j] = 0.0f;

    for (int kb = k0; kb < k1; kb += KT) {
        for (int i = tid; i < 64 * KT; i += 256) {
            int mm = i / KT, kk = i % KT;
            int kg = kb + kk;
            int mg = m0 + mm;
            As[mm][kk] = (kg < k1 && mg < M) ? A[(size_t)mg * K + kg] : 0.0f;
        }
        for (int i = tid; i < KT * 64; i += 256) {
            int kk = i / 64, nn = i % 64;
            int kg = kb + kk;
            Bs[kk][nn] = (kg < k1) ? B[(size_t)kg * N + n0 + nn] : 0.0f;
        }
        __syncthreads();
#pragma unroll
        for (int kk = 0; kk < KT; kk++) {
            float a[4], b[4];
#pragma unroll
            for (int i = 0; i < 4; i++) a[i] = As[tm * 4 + i][kk];
#pragma unroll
            for (int j = 0; j < 4; j++) b[j] = Bs[kk][tn * 4 + j];
#pragma unroll
            for (int i = 0; i < 4; i++)
#pragma unroll
                for (int j = 0; j < 4; j++) acc[i][j] += a[i] * b[j];
        }
        __syncthreads();
    }

    float* P = g_part + (size_t)s * M * N;
#pragma unroll
    for (int i = 0; i < 4; i++) {
        int m = m0 + tm * 4 + i;
        if (m < M) {
#pragma unroll
            for (int j = 0; j < 4; j++) {
                int n = n0 + tn * 4 + j;
                P[(size_t)m * N + n] = acc[i][j];
            }
        }
    }
}

// ---------------- combine split-K + bias + BatchNorm(train) + optional ReLU ----------
// grid = N columns, block = M (=R) threads; M must be power of two (256)
__global__ void bn_combine_kernel(const float* __restrict__ bias,
                                  const float* __restrict__ gam,
                                  const float* __restrict__ bet,
                                  float* __restrict__ out,
                                  int M, int N, int S, int relu) {
    int n = blockIdx.x;
    int m = threadIdx.x;
    __shared__ float red[1024];

    float v = bias[n];
    for (int s = 0; s < S; s++)
        v += g_part[(size_t)s * M * N + (size_t)m * N + n];

    red[m] = v;
    __syncthreads();
    for (int st = blockDim.x >> 1; st > 0; st >>= 1) {
        if (m < st) red[m] += red[m + st];
        __syncthreads();
    }
    float mean = red[0] / (float)M;
    __syncthreads();

    float d = v - mean;
    red[m] = d * d;
    __syncthreads();
    for (int st = blockDim.x >> 1; st > 0; st >>= 1) {
        if (m < st) red[m] += red[m + st];
        __syncthreads();
    }
    float var = red[0] / (float)M;

    float y = gam[n] * d * rsqrtf(var + 1e-5f) + bet[n];
    if (relu) y = fmaxf(y, 0.0f);
    out[(size_t)m * N + n] = y;
}

// ---------------- host ----------------
static void run_layer(const float* X, const float* W, const float* b,
                      const float* g, const float* be, float* Y,
                      int M, int K, int N, int S, int relu) {
    int chunk = (K + S - 1) / S;
    dim3 grid(N / 64, (M + 63) / 64, S);
    gemm_splitk_kernel<<<grid, 256>>>(X, W, M, N, K, chunk);
    bn_combine_kernel<<<N, M>>>(b, g, be, Y, M, N, S, relu);
}

extern "C" void kernel_launch(void* const* d_in, const int* in_sizes, int n_in,
                              void* d_out, int out_size) {
    const int*   roi_idx = (const int*)d_in[1];
    const float* feats   = (const float*)d_in[2];
    const float* coords  = (const float*)d_in[3];
    const float* w1 = (const float*)d_in[4],  *b1 = (const float*)d_in[5];
    const float* g1 = (const float*)d_in[6],  *be1 = (const float*)d_in[7];
    const float* w2 = (const float*)d_in[8],  *b2 = (const float*)d_in[9];
    const float* g2 = (const float*)d_in[10], *be2 = (const float*)d_in[11];
    const float* w3 = (const float*)d_in[12], *b3 = (const float*)d_in[13];
    const float* g3 = (const float*)d_in[14], *be3 = (const float*)d_in[15];
    const float* w4 = (const float*)d_in[16], *b4 = (const float*)d_in[17];
    const float* g4 = (const float*)d_in[18], *be4 = (const float*)d_in[19];
    const float* w5 = (const float*)d_in[20], *b5 = (const float*)d_in[21];
    const float* g5 = (const float*)d_in[22], *be5 = (const float*)d_in[23];

    int R  = out_size / 512;   // output is [R, 512]
    int Np = in_sizes[1];      // number of points

    float* out = (float*)d_out;

    // resolve device scratch pointers for the MLP stages
    float *feat_p, *hA_p, *hB_p;
    cudaGetSymbolAddress((void**)&feat_p, g_feat);
    cudaGetSymbolAddress((void**)&hA_p,  g_hA);
    cudaGetSymbolAddress((void**)&hB_p,  g_hB);

    const int FPS_SMEM = PCAP * 5 * (int)sizeof(float);  // 80KB
    cudaFuncSetAttribute(fps_kernel, cudaFuncAttributeMaxDynamicSharedMemorySize, FPS_SMEM);

    // ---- grouping ----
    zero_counts_kernel<<<1, 256>>>(R);
    hist_kernel<<<(Np + 255) / 256, 256>>>(roi_idx, Np);
    scan_kernel<<<1, R>>>(R);
    scatter_kernel<<<(Np + 255) / 256, 256>>>(roi_idx, coords, Np);

    // ---- FPS + gather ----
    fps_kernel<<<R, 256, FPS_SMEM>>>(KSEL);
    gather_kernel<<<R, 256>>>(feats, KSEL, FDIM);

    // ---- MLP ----
    run_layer(feat_p, w1, b1, g1, be1, hA_p, R, KSEL * FDIM, 256, 12, 1);
    run_layer(hA_p,   w2, b2, g2, be2, hB_p, R, 256,          256, 4,  1);
    run_layer(hB_p,   w3, b3, g3, be3, hA_p, R, 256,          512, 4,  0);
    run_layer(hA_p,   w4, b4, g4, be4, hB_p, R, 512,          256, 4,  1);
    run_layer(hB_p,   w5, b5, g5, be5, out,  R, 256,          512, 4,  1);
}

// round 2
// speedup vs baseline: 1.6980x; 1.6980x over previous
#include <cuda_runtime.h>
#include <cuda_bf16.h>
#include <math.h>
#include <limits.h>

// ---------------- problem constants ----------------
#define KSEL   50          // NUM_POINTS
#define FDIM   90          // feature dim
#define PCAP   4096        // PMAX
#define RMAX   256
#define NMAX   600000
#define SMAX   16          // max split-K slices
#define NB     240         // grouping blocks (private histograms)

// ---------------- device scratch (no allocs allowed) ----------------
__device__ int    g_counts[RMAX];
__device__ int    g_offsets[RMAX];
__device__ int    g_bc[NB * RMAX];       // per-block histograms
__device__ int    g_bbase[NB * RMAX];    // per-(block,roi) scatter base
__device__ float4 g_packed[NMAX];
__device__ int    g_sel[RMAX * KSEL];
__device__ float  g_feat[RMAX * KSEL * FDIM];       // [R, 4500]
__device__ float  g_part[SMAX * RMAX * 512];        // split-K partials
__device__ float  g_hA[RMAX * 512];
__device__ float  g_hB[RMAX * 512];

// ---------------- phase A: per-block private histogram ----------------
__global__ void blockhist_kernel(const int* __restrict__ idx, int Np, int chunk) {
    __shared__ int sh[RMAX];
    int b = blockIdx.x;
    int t = threadIdx.x;
    sh[t] = 0;
    __syncthreads();
    int i0 = b * chunk;
    int i1 = i0 + chunk; if (i1 > Np) i1 = Np;
    for (int i = i0 + t; i < i1; i += blockDim.x)
        atomicAdd(&sh[idx[i]], 1);
    __syncthreads();
    g_bc[b * RMAX + t] = sh[t];
}

// ---------------- phase B1: column totals + exclusive scan over ROIs ------
// single block, 256 threads (thread = roi)
__global__ void totals_scan_kernel() {
    __shared__ int tmp[RMAX];
    int r = threadIdx.x;
    int c = 0;
    for (int b = 0; b < NB; b++) c += g_bc[b * RMAX + r];
    g_counts[r] = c;
    tmp[r] = c;
    __syncthreads();
    for (int o = 1; o < RMAX; o <<= 1) {
        int x = (r >= o) ? tmp[r - o] : 0;
        __syncthreads();
        tmp[r] += x;
        __syncthreads();
    }
    g_offsets[r] = tmp[r] - c;
}

// ---------------- phase B2: per-(block,roi) base offsets ----------------
// grid = RMAX (one per roi), block = 256 threads (thread = grouping block id)
__global__ void blockbase_kernel() {
    __shared__ int tmp[256];
    int r = blockIdx.x;
    int t = threadIdx.x;
    int v = (t < NB) ? g_bc[t * RMAX + r] : 0;
    tmp[t] = v;
    __syncthreads();
    for (int o = 1; o < 256; o <<= 1) {
        int x = (t >= o) ? tmp[t - o] : 0;
        __syncthreads();
        tmp[t] += x;
        __syncthreads();
    }
    if (t < NB) g_bbase[t * RMAX + r] = g_offsets[r] + tmp[t] - v;
}

// ---------------- phase C: scatter with smem cursors ----------------
__global__ void scatter_kernel(const int* __restrict__ idx,
                               const float* __restrict__ coords,
                               int Np, int chunk) {
    __shared__ int sc[RMAX];
    int b = blockIdx.x;
    int t = threadIdx.x;
    sc[t] = g_bbase[b * RMAX + t];
    __syncthreads();
    int i0 = b * chunk;
    int i1 = i0 + chunk; if (i1 > Np) i1 = Np;
    for (int i = i0 + t; i < i1; i += blockDim.x) {
        int r = idx[i];
        int slot = atomicAdd(&sc[r], 1);
        float4 p;
        p.x = coords[3 * i + 0];
        p.y = coords[3 * i + 1];
        p.z = coords[3 * i + 2];
        p.w = __int_as_float(i);
        g_packed[slot] = p;
    }
}

// ---------------- FPS: one block per ROI ----------------
// dynamic smem: sx,sy,sz,sd (float[PCAP] each) + sid (int[PCAP]) = 80KB
__global__ void fps_kernel(int K) {
    extern __shared__ float sm[];
    float* sx  = sm;
    float* sy  = sx + PCAP;
    float* sz  = sy + PCAP;
    float* sd  = sz + PCAP;
    int*   sid = (int*)(sd + PCAP);

    __shared__ float rv[16];
    __shared__ int   rid[16], rpos[16];
    __shared__ float lastx, lasty, lastz;

    int r = blockIdx.x;
    int P = g_counts[r];
    if (P > PCAP) P = PCAP;
    if (P == 0) return;
    int off = g_offsets[r];
    int tid = threadIdx.x;
    int nw  = blockDim.x >> 5;

    for (int j = tid; j < P; j += blockDim.x) {
        float4 p = g_packed[off + j];
        sx[j] = p.x; sy[j] = p.y; sz[j] = p.z;
        sid[j] = __float_as_int(p.w);
        sd[j] = 1e10f;
    }
    __syncthreads();

    // first selection: minimum global id (== reference's stable position 0)
    {
        int bi = INT_MAX, bp = -1;
        for (int j = tid; j < P; j += blockDim.x) {
            int id = sid[j];
            if (id < bi) { bi = id; bp = j; }
        }
        for (int o = 16; o > 0; o >>= 1) {
            int oi = __shfl_down_sync(~0u, bi, o);
            int op = __shfl_down_sync(~0u, bp, o);
            if (oi < bi) { bi = oi; bp = op; }
        }
        if ((tid & 31) == 0) { rid[tid >> 5] = bi; rpos[tid >> 5] = bp; }
        __syncthreads();
        if (tid == 0) {
            int BI = rid[0], BP = rpos[0];
            for (int w = 1; w < nw; w++)
                if (rid[w] < BI) { BI = rid[w]; BP = rpos[w]; }
            g_sel[r * K + 0] = BI;
            lastx = sx[BP]; lasty = sy[BP]; lastz = sz[BP];
        }
        __syncthreads();
    }

    for (int it = 1; it < K; it++) {
        float lx = lastx, ly = lasty, lz = lastz;
        float bv = -2.0f; int bi = INT_MAX; int bp = -1;
        for (int j = tid; j < P; j += blockDim.x) {
            float dx = sx[j] - lx, dy = sy[j] - ly, dz = sz[j] - lz;
            float d  = dx * dx + dy * dy + dz * dz;
            float nd = fminf(sd[j], d);
            sd[j] = nd;
            int id = sid[j];
            if (nd > bv || (nd == bv && id < bi)) { bv = nd; bi = id; bp = j; }
        }
        for (int o = 16; o > 0; o >>= 1) {
            float ov = __shfl_down_sync(~0u, bv, o);
            int   oi = __shfl_down_sync(~0u, bi, o);
            int   op = __shfl_down_sync(~0u, bp, o);
            if (ov > bv || (ov == bv && oi < bi)) { bv = ov; bi = oi; bp = op; }
        }
        if ((tid & 31) == 0) { rv[tid >> 5] = bv; rid[tid >> 5] = bi; rpos[tid >> 5] = bp; }
        __syncthreads();
        if (tid == 0) {
            float BV = rv[0]; int BI = rid[0], BP = rpos[0];
            for (int w = 1; w < nw; w++) {
                if (rv[w] > BV || (rv[w] == BV && rid[w] < BI)) {
                    BV = rv[w]; BI = rid[w]; BP = rpos[w];
                }
            }
            g_sel[r * K + it] = BI;
            lastx = sx[BP]; lasty = sy[BP]; lastz = sz[BP];
        }
        __syncthreads();
    }
}

// ---------------- feature gather ----------------
__global__ void gather_kernel(const float* __restrict__ feats, int K, int F) {
    int r = blockIdx.x;
    int tot = K * F;
    bool zero = (g_counts[r] == 0);
    for (int e = threadIdx.x; e < tot; e += blockDim.x) {
        float v = 0.0f;
        if (!zero) {
            int k = e / F;
            int f = e - k * F;
            v = feats[(size_t)g_sel[r * K + k] * F + f];
        }
        g_feat[(size_t)r * tot + e] = v;
    }
}

// ---------------- split-K SGEMM: 64x64 tile, 4x4 microtile, 256 threads ----------------
#define KT 16
__global__ void gemm_splitk_kernel(const float* __restrict__ A,
                                   const float* __restrict__ B,
                                   int M, int N, int K, int chunk) {
    __shared__ float As[64][KT + 1];
    __shared__ float Bs[KT][64 + 1];
    int s  = blockIdx.z;
    int k0 = s * chunk;
    int k1 = k0 + chunk; if (k1 > K) k1 = K;
    int m0 = blockIdx.y * 64, n0 = blockIdx.x * 64;
    int tid = threadIdx.x;
    int tn = tid & 15, tm = tid >> 4;

    float acc[4][4];
#pragma unroll
    for (int i = 0; i < 4; i++)
#pragma unroll
        for (int j = 0; j < 4; j++) acc[i][j] = 0.0f;

    for (int kb = k0; kb < k1; kb += KT) {
        for (int i = tid; i < 64 * KT; i += 256) {
            int mm = i / KT, kk = i % KT;
            int kg = kb + kk;
            int mg = m0 + mm;
            As[mm][kk] = (kg < k1 && mg < M) ? A[(size_t)mg * K + kg] : 0.0f;
        }
        for (int i = tid; i < KT * 64; i += 256) {
            int kk = i / 64, nn = i % 64;
            int kg = kb + kk;
            Bs[kk][nn] = (kg < k1) ? B[(size_t)kg * N + n0 + nn] : 0.0f;
        }
        __syncthreads();
#pragma unroll
        for (int kk = 0; kk < KT; kk++) {
            float a[4], b[4];
#pragma unroll
            for (int i = 0; i < 4; i++) a[i] = As[tm * 4 + i][kk];
#pragma unroll
            for (int j = 0; j < 4; j++) b[j] = Bs[kk][tn * 4 + j];
#pragma unroll
            for (int i = 0; i < 4; i++)
#pragma unroll
                for (int j = 0; j < 4; j++) acc[i][j] += a[i] * b[j];
        }
        __syncthreads();
    }

    float* P = g_part + (size_t)s * M * N;
#pragma unroll
    for (int i = 0; i < 4; i++) {
        int m = m0 + tm * 4 + i;
        if (m < M) {
#pragma unroll
            for (int j = 0; j < 4; j++) {
                int n = n0 + tn * 4 + j;
                P[(size_t)m * N + n] = acc[i][j];
            }
        }
    }
}

// ---------------- combine split-K + bias + BatchNorm(train) + optional ReLU ----------
// grid = N columns, block = M (=R) threads; M must be power of two (256)
__global__ void bn_combine_kernel(const float* __restrict__ bias,
                                  const float* __restrict__ gam,
                                  const float* __restrict__ bet,
                                  float* __restrict__ out,
                                  int M, int N, int S, int relu) {
    int n = blockIdx.x;
    int m = threadIdx.x;
    __shared__ float red[1024];

    float v = bias[n];
    for (int s = 0; s < S; s++)
        v += g_part[(size_t)s * M * N + (size_t)m * N + n];

    red[m] = v;
    __syncthreads();
    for (int st = blockDim.x >> 1; st > 0; st >>= 1) {
        if (m < st) red[m] += red[m + st];
        __syncthreads();
    }
    float mean = red[0] / (float)M;
    __syncthreads();

    float d = v - mean;
    red[m] = d * d;
    __syncthreads();
    for (int st = blockDim.x >> 1; st > 0; st >>= 1) {
        if (m < st) red[m] += red[m + st];
        __syncthreads();
    }
    float var = red[0] / (float)M;

    float y = gam[n] * d * rsqrtf(var + 1e-5f) + bet[n];
    if (relu) y = fmaxf(y, 0.0f);
    out[(size_t)m * N + n] = y;
}

// ---------------- host ----------------
static void run_layer(const float* X, const float* W, const float* b,
                      const float* g, const float* be, float* Y,
                      int M, int K, int N, int S, int relu) {
    int chunk = (K + S - 1) / S;
    dim3 grid(N / 64, (M + 63) / 64, S);
    gemm_splitk_kernel<<<grid, 256>>>(X, W, M, N, K, chunk);
    bn_combine_kernel<<<N, M>>>(b, g, be, Y, M, N, S, relu);
}

extern "C" void kernel_launch(void* const* d_in, const int* in_sizes, int n_in,
                              void* d_out, int out_size) {
    const int*   roi_idx = (const int*)d_in[1];
    const float* feats   = (const float*)d_in[2];
    const float* coords  = (const float*)d_in[3];
    const float* w1 = (const float*)d_in[4],  *b1 = (const float*)d_in[5];
    const float* g1 = (const float*)d_in[6],  *be1 = (const float*)d_in[7];
    const float* w2 = (const float*)d_in[8],  *b2 = (const float*)d_in[9];
    const float* g2 = (const float*)d_in[10], *be2 = (const float*)d_in[11];
    const float* w3 = (const float*)d_in[12], *b3 = (const float*)d_in[13];
    const float* g3 = (const float*)d_in[14], *be3 = (const float*)d_in[15];
    const float* w4 = (const float*)d_in[16], *b4 = (const float*)d_in[17];
    const float* g4 = (const float*)d_in[18], *be4 = (const float*)d_in[19];
    const float* w5 = (const float*)d_in[20], *b5 = (const float*)d_in[21];
    const float* g5 = (const float*)d_in[22], *be5 = (const float*)d_in[23];

    int R  = out_size / 512;   // output is [R, 512]
    int Np = in_sizes[1];      // number of points

    float* out = (float*)d_out;

    // resolve device scratch pointers for the MLP stages
    float *feat_p, *hA_p, *hB_p;
    cudaGetSymbolAddress((void**)&feat_p, g_feat);
    cudaGetSymbolAddress((void**)&hA_p,  g_hA);
    cudaGetSymbolAddress((void**)&hB_p,  g_hB);

    const int FPS_SMEM = PCAP * 5 * (int)sizeof(float);  // 80KB
    cudaFuncSetAttribute(fps_kernel, cudaFuncAttributeMaxDynamicSharedMemorySize, FPS_SMEM);

    // ---- grouping (privatized, no global atomics) ----
    int chunk = (Np + NB - 1) / NB;
    blockhist_kernel<<<NB, 256>>>(roi_idx, Np, chunk);
    totals_scan_kernel<<<1, 256>>>();
    blockbase_kernel<<<RMAX, 256>>>();
    scatter_kernel<<<NB, 256>>>(roi_idx, coords, Np, chunk);

    // ---- FPS + gather ----
    fps_kernel<<<R, 512, FPS_SMEM>>>(KSEL);
    gather_kernel<<<R, 256>>>(feats, KSEL, FDIM);

    // ---- MLP ----
    run_layer(feat_p, w1, b1, g1, be1, hA_p, R, KSEL * FDIM, 256, 12, 1);
    run_layer(hA_p,   w2, b2, g2, be2, hB_p, R, 256,          256, 4,  1);
    run_layer(hB_p,   w3, b3, g3, be3, hA_p, R, 256,          512, 4,  0);
    run_layer(hA_p,   w4, b4, g4, be4, hB_p, R, 512,          256, 4,  1);
    run_layer(hB_p,   w5, b5, g5, be5, out,  R, 256,          512, 4,  1);
}

// round 3
// speedup vs baseline: 2.8384x; 1.6717x over previous
#include <cuda_runtime.h>
#include <cuda_bf16.h>
#include <math.h>
#include <limits.h>

// ---------------- problem constants ----------------
#define KSEL   50          // NUM_POINTS
#define FDIM   90          // feature dim
#define PCAP   4096        // PMAX
#define RMAX   256
#define NMAX   600000
#define SMAX   16          // max split-K slices
#define NB     240         // grouping blocks (private histograms)

// ---------------- device scratch (no allocs allowed) ----------------
__device__ int    g_counts[RMAX];
__device__ int    g_offsets[RMAX];
__device__ int    g_bc[NB * RMAX];       // per-block histograms
__device__ int    g_bbase[NB * RMAX];    // per-(block,roi) scatter base
__device__ float4 g_packed[NMAX];
__device__ float  g_feat[RMAX * KSEL * FDIM];       // [R, 4500]
__device__ float  g_part[SMAX * RMAX * 512];        // split-K partials
__device__ float  g_hA[RMAX * 512];
__device__ float  g_hB[RMAX * 512];

// ---------------- phase A: per-block private histogram ----------------
__global__ void blockhist_kernel(const int* __restrict__ idx, int Np, int chunk) {
    __shared__ int sh[RMAX];
    int b = blockIdx.x;
    int t = threadIdx.x;
    if (t < RMAX) sh[t] = 0;
    __syncthreads();
    int i0 = b * chunk;
    int i1 = i0 + chunk; if (i1 > Np) i1 = Np;
    for (int i = i0 + t; i < i1; i += blockDim.x)
        atomicAdd(&sh[idx[i]], 1);
    __syncthreads();
    if (t < RMAX) g_bc[b * RMAX + t] = sh[t];
}

// ---------------- phase B1: column totals + exclusive scan over ROIs ------
__global__ void totals_scan_kernel() {
    __shared__ int tmp[RMAX];
    int r = threadIdx.x;
    int c = 0;
    for (int b = 0; b < NB; b++) c += g_bc[b * RMAX + r];
    g_counts[r] = c;
    tmp[r] = c;
    __syncthreads();
    for (int o = 1; o < RMAX; o <<= 1) {
        int x = (r >= o) ? tmp[r - o] : 0;
        __syncthreads();
        tmp[r] += x;
        __syncthreads();
    }
    g_offsets[r] = tmp[r] - c;
}

// ---------------- phase B2: per-(block,roi) base offsets ----------------
__global__ void blockbase_kernel() {
    __shared__ int tmp[256];
    int r = blockIdx.x;
    int t = threadIdx.x;
    int v = (t < NB) ? g_bc[t * RMAX + r] : 0;
    tmp[t] = v;
    __syncthreads();
    for (int o = 1; o < 256; o <<= 1) {
        int x = (t >= o) ? tmp[t - o] : 0;
        __syncthreads();
        tmp[t] += x;
        __syncthreads();
    }
    if (t < NB) g_bbase[t * RMAX + r] = g_offsets[r] + tmp[t] - v;
}

// ---------------- phase C: scatter with smem cursors ----------------
__global__ void scatter_kernel(const int* __restrict__ idx,
                               const float* __restrict__ coords,
                               int Np, int chunk) {
    __shared__ int sc[RMAX];
    int b = blockIdx.x;
    int t = threadIdx.x;
    if (t < RMAX) sc[t] = g_bbase[b * RMAX + t];
    __syncthreads();
    int i0 = b * chunk;
    int i1 = i0 + chunk; if (i1 > Np) i1 = Np;
    for (int i = i0 + t; i < i1; i += blockDim.x) {
        int r = idx[i];
        int slot = atomicAdd(&sc[r], 1);
        float4 p;
        p.x = coords[3 * i + 0];
        p.y = coords[3 * i + 1];
        p.z = coords[3 * i + 2];
        p.w = __int_as_float(i);
        g_packed[slot] = p;
    }
}

// ---------------- FPS (+fused gather): one block (512 thr) per ROI ----------------
// dynamic smem: sx,sy,sz (float[PCAP]) + sid (int[PCAP]) = 64KB
#define FPW 8   // PCAP / 512
__global__ __launch_bounds__(512, 2) void fps_kernel(const float* __restrict__ feats) {
    extern __shared__ float sm[];
    float* sx  = sm;
    float* sy  = sx + PCAP;
    float* sz  = sy + PCAP;
    int*   sid = (int*)(sz + PCAP);

    __shared__ float rv[16];
    __shared__ int   rid[16], rpos[16];
    __shared__ float lastx, lasty, lastz;
    __shared__ int   ssel[KSEL];

    int r = blockIdx.x;
    int P = g_counts[r];
    if (P > PCAP) P = PCAP;
    int tid = threadIdx.x;

    if (P == 0) {
        for (int e = tid; e < KSEL * FDIM; e += 512)
            g_feat[(size_t)r * (KSEL * FDIM) + e] = 0.0f;
        return;
    }
    int off = g_offsets[r];

    // register-resident point data
    float rx[FPW], ry[FPW], rz[FPW], rd[FPW];
    int   rgid[FPW];

#pragma unroll
    for (int jj = 0; jj < FPW; jj++) {
        int j = tid + jj * 512;
        if (j < P) {
            float4 p = g_packed[off + j];
            rx[jj] = p.x; ry[jj] = p.y; rz[jj] = p.z;
            rgid[jj] = __float_as_int(p.w);
            sx[j] = p.x; sy[j] = p.y; sz[j] = p.z;
            sid[j] = rgid[jj];
        }
        rd[jj] = 1e10f;
    }
    __syncthreads();

    // first selection: minimum global id
    {
        int bi = INT_MAX, bp = -1;
#pragma unroll
        for (int jj = 0; jj < FPW; jj++) {
            int j = tid + jj * 512;
            if (j < P && rgid[jj] < bi) { bi = rgid[jj]; bp = j; }
        }
        for (int o = 16; o > 0; o >>= 1) {
            int oi = __shfl_down_sync(~0u, bi, o);
            int op = __shfl_down_sync(~0u, bp, o);
            if (oi < bi) { bi = oi; bp = op; }
        }
        if ((tid & 31) == 0) { rid[tid >> 5] = bi; rpos[tid >> 5] = bp; }
        __syncthreads();
        if (tid < 32) {
            int v  = (tid < 16) ? rid[tid]  : INT_MAX;
            int pp = (tid < 16) ? rpos[tid] : -1;
            for (int o = 8; o > 0; o >>= 1) {
                int oi = __shfl_down_sync(~0u, v, o);
                int op = __shfl_down_sync(~0u, pp, o);
                if (oi < v) { v = oi; pp = op; }
            }
            if (tid == 0) {
                ssel[0] = v;
                lastx = sx[pp]; lasty = sy[pp]; lastz = sz[pp];
            }
        }
        __syncthreads();
    }

    for (int it = 1; it < KSEL; it++) {
        float lx = lastx, ly = lasty, lz = lastz;
        float bv = -2.0f; int bi = INT_MAX; int bp = -1;
#pragma unroll
        for (int jj = 0; jj < FPW; jj++) {
            int j = tid + jj * 512;
            if (j < P) {
                float dx = rx[jj] - lx, dy = ry[jj] - ly, dz = rz[jj] - lz;
                float d  = dx * dx + dy * dy + dz * dz;
                float nd = fminf(rd[jj], d);
                rd[jj] = nd;
                if (nd > bv || (nd == bv && rgid[jj] < bi)) { bv = nd; bi = rgid[jj]; bp = j; }
            }
        }
        for (int o = 16; o > 0; o >>= 1) {
            float ov = __shfl_down_sync(~0u, bv, o);
            int   oi = __shfl_down_sync(~0u, bi, o);
            int   op = __shfl_down_sync(~0u, bp, o);
            if (ov > bv || (ov == bv && oi < bi)) { bv = ov; bi = oi; bp = op; }
        }
        if ((tid & 31) == 0) { rv[tid >> 5] = bv; rid[tid >> 5] = bi; rpos[tid >> 5] = bp; }
        __syncthreads();
        if (tid < 32) {
            float v  = (tid < 16) ? rv[tid]   : -3.0f;
            int   id = (tid < 16) ? rid[tid]  : INT_MAX;
            int   pp = (tid < 16) ? rpos[tid] : -1;
            for (int o = 8; o > 0; o >>= 1) {
                float ov = __shfl_down_sync(~0u, v, o);
                int   oi = __shfl_down_sync(~0u, id, o);
                int   op = __shfl_down_sync(~0u, pp, o);
                if (ov > v || (ov == v && oi < id)) { v = ov; id = oi; pp = op; }
            }
            if (tid == 0) {
                ssel[it] = id;
                lastx = sx[pp]; lasty = sy[pp]; lastz = sz[pp];
            }
        }
        __syncthreads();
    }

    // fused feature gather: [KSEL, FDIM] row for this ROI
    for (int e = tid; e < KSEL * FDIM; e += 512) {
        int k = e / FDIM;
        int f = e - k * FDIM;
        g_feat[(size_t)r * (KSEL * FDIM) + e] = feats[(size_t)ssel[k] * FDIM + f];
    }
}

// ---------------- tensor-core split-K GEMM (3xTF32) ----------------
// block 128 thr (4 warps), tile 64(M) x 64(N), KT=32
__device__ __forceinline__ void split_tf32(float x, unsigned& hi, unsigned& lo) {
    unsigned h;
    asm("cvt.rna.tf32.f32 %0, %1;" : "=r"(h) : "f"(x));
    float rres = x - __uint_as_float(h);
    unsigned l;
    asm("cvt.rna.tf32.f32 %0, %1;" : "=r"(l) : "f"(rres));
    hi = h; lo = l;
}

#define MMA_TF32(D, A0, A1, A2, A3, B0, B1)                                   \
    asm volatile("mma.sync.aligned.m16n8k8.row.col.f32.tf32.tf32.f32 "        \
                 "{%0,%1,%2,%3},{%4,%5,%6,%7},{%8,%9},{%0,%1,%2,%3};"         \
                 : "+f"(D[0]), "+f"(D[1]), "+f"(D[2]), "+f"(D[3])             \
                 : "r"(A0), "r"(A1), "r"(A2), "r"(A3), "r"(B0), "r"(B1))

__global__ __launch_bounds__(128) void gemm_tc_kernel(const float* __restrict__ A,
                                                      const float* __restrict__ B,
                                                      int M, int N, int K, int chunk) {
    __shared__ float As[64][36];
    __shared__ float Bs[32][72];
    int s  = blockIdx.z;
    int k0 = s * chunk;
    int k1 = k0 + chunk; if (k1 > K) k1 = K;
    int m0 = blockIdx.y * 64, n0 = blockIdx.x * 64;
    int tid = threadIdx.x;
    int lane = tid & 31, w = tid >> 5;
    int wm = w >> 1, wn = w & 1;
    int g = lane >> 2, q = lane & 3;

    float d[2][4][4];
#pragma unroll
    for (int mi = 0; mi < 2; mi++)
#pragma unroll
        for (int ni = 0; ni < 4; ni++)
#pragma unroll
            for (int e = 0; e < 4; e++) d[mi][ni][e] = 0.0f;

    for (int kb = k0; kb < k1; kb += 32) {
        if (kb + 32 <= k1) {
#pragma unroll
            for (int i = 0; i < 4; i++) {
                int id = tid + i * 128;
                int row = id >> 3, c4 = id & 7;
                float4 v = *(const float4*)&A[(size_t)(m0 + row) * K + kb + c4 * 4];
                *(float4*)&As[row][c4 * 4] = v;
            }
#pragma unroll
            for (int i = 0; i < 4; i++) {
                int id = tid + i * 128;
                int row = id >> 4, c4 = id & 15;
                float4 v = *(const float4*)&B[(size_t)(kb + row) * N + n0 + c4 * 4];
                *(float4*)&Bs[row][c4 * 4] = v;
            }
        } else {
            for (int i = tid; i < 64 * 32; i += 128) {
                int row = i >> 5, c = i & 31;
                int kg = kb + c;
                As[row][c] = (kg < k1) ? A[(size_t)(m0 + row) * K + kg] : 0.0f;
            }
            for (int i = tid; i < 32 * 64; i += 128) {
                int row = i >> 6, c = i & 63;
                int kg = kb + row;
                Bs[row][c] = (kg < k1) ? B[(size_t)kg * N + n0 + c] : 0.0f;
            }
        }
        __syncthreads();
#pragma unroll
        for (int k8 = 0; k8 < 32; k8 += 8) {
            unsigned ah[2][4], al[2][4], bh[4][2], bl[4][2];
#pragma unroll
            for (int mi = 0; mi < 2; mi++) {
                int r0 = wm * 32 + mi * 16 + g;
                split_tf32(As[r0][k8 + q],         ah[mi][0], al[mi][0]);
                split_tf32(As[r0 + 8][k8 + q],     ah[mi][1], al[mi][1]);
                split_tf32(As[r0][k8 + q + 4],     ah[mi][2], al[mi][2]);
                split_tf32(As[r0 + 8][k8 + q + 4], ah[mi][3], al[mi][3]);
            }
#pragma unroll
            for (int ni = 0; ni < 4; ni++) {
                int col = wn * 32 + ni * 8 + g;
                split_tf32(Bs[k8 + q][col],     bh[ni][0], bl[ni][0]);
                split_tf32(Bs[k8 + q + 4][col], bh[ni][1], bl[ni][1]);
            }
#pragma unroll
            for (int mi = 0; mi < 2; mi++)
#pragma unroll
                for (int ni = 0; ni < 4; ni++) {
                    MMA_TF32(d[mi][ni], ah[mi][0], ah[mi][1], ah[mi][2], ah[mi][3],
                             bh[ni][0], bh[ni][1]);
                    MMA_TF32(d[mi][ni], ah[mi][0], ah[mi][1], ah[mi][2], ah[mi][3],
                             bl[ni][0], bl[ni][1]);
                    MMA_TF32(d[mi][ni], al[mi][0], al[mi][1], al[mi][2], al[mi][3],
                             bh[ni][0], bh[ni][1]);
                }
        }
        __syncthreads();
    }

    float* P = g_part + (size_t)s * M * N;
#pragma unroll
    for (int mi = 0; mi < 2; mi++) {
#pragma unroll
        for (int ni = 0; ni < 4; ni++) {
            int m_ = m0 + wm * 32 + mi * 16 + g;
            int n_ = n0 + wn * 32 + ni * 8 + q * 2;
            *(float2*)&P[(size_t)m_ * N + n_]       = make_float2(d[mi][ni][0], d[mi][ni][1]);
            *(float2*)&P[(size_t)(m_ + 8) * N + n_] = make_float2(d[mi][ni][2], d[mi][ni][3]);
        }
    }
}

// ---------------- combine split-K + bias + BatchNorm(train) + optional ReLU ----------
// block 256 thr handles 8 columns x all M=256 rows; grid = N/8
__global__ __launch_bounds__(256) void bn_combine_kernel(const float* __restrict__ bias,
                                                         const float* __restrict__ gam,
                                                         const float* __restrict__ bet,
                                                         float* __restrict__ out,
                                                         int M, int N, int S, int relu) {
    __shared__ float red[256];
    __shared__ float cmean[8], cvar[8];
    int t = threadIdx.x;
    int n0 = blockIdx.x * 8;
    int col = n0 + (t & 7);
    int mrow = t >> 3;          // 0..31, this thread handles rows mrow + 32*j

    float bn = bias[col];
    float v[8];
    float psum = 0.0f;
#pragma unroll
    for (int j = 0; j < 8; j++) {
        int m = mrow + 32 * j;
        float acc = bn;
        for (int s = 0; s < S; s++)
            acc += g_part[(size_t)s * M * N + (size_t)m * N + col];
        v[j] = acc;
        psum += acc;
    }
    red[t] = psum;
    __syncthreads();
    for (int st = 128; st >= 8; st >>= 1) {
        if (t < st) red[t] += red[t + st];
        __syncthreads();
    }
    if (t < 8) cmean[t] = red[t] / (float)M;
    __syncthreads();
    float mean = cmean[t & 7];

    float pss = 0.0f;
#pragma unroll
    for (int j = 0; j < 8; j++) {
        float dd = v[j] - mean;
        pss += dd * dd;
    }
    red[t] = pss;
    __syncthreads();
    for (int st = 128; st >= 8; st >>= 1) {
        if (t < st) red[t] += red[t + st];
        __syncthreads();
    }
    if (t < 8) cvar[t] = red[t] / (float)M;
    __syncthreads();
    float inv = rsqrtf(cvar[t & 7] + 1e-5f);
    float gm = gam[col], bt = bet[col];

#pragma unroll
    for (int j = 0; j < 8; j++) {
        int m = mrow + 32 * j;
        float y = gm * (v[j] - mean) * inv + bt;
        if (relu) y = fmaxf(y, 0.0f);
        out[(size_t)m * N + col] = y;
    }
}

// ---------------- host ----------------
static void run_layer(const float* X, const float* W, const float* b,
                      const float* g, const float* be, float* Y,
                      int M, int K, int N, int S, int relu) {
    int chunk = ((K + S - 1) / S + 31) & ~31;
    dim3 grid(N / 64, M / 64, S);
    gemm_tc_kernel<<<grid, 128>>>(X, W, M, N, K, chunk);
    bn_combine_kernel<<<N / 8, 256>>>(b, g, be, Y, M, N, S, relu);
}

extern "C" void kernel_launch(void* const* d_in, const int* in_sizes, int n_in,
                              void* d_out, int out_size) {
    const int*   roi_idx = (const int*)d_in[1];
    const float* feats   = (const float*)d_in[2];
    const float* coords  = (const float*)d_in[3];
    const float* w1 = (const float*)d_in[4],  *b1 = (const float*)d_in[5];
    const float* g1 = (const float*)d_in[6],  *be1 = (const float*)d_in[7];
    const float* w2 = (const float*)d_in[8],  *b2 = (const float*)d_in[9];
    const float* g2 = (const float*)d_in[10], *be2 = (const float*)d_in[11];
    const float* w3 = (const float*)d_in[12], *b3 = (const float*)d_in[13];
    const float* g3 = (const float*)d_in[14], *be3 = (const float*)d_in[15];
    const float* w4 = (const float*)d_in[16], *b4 = (const float*)d_in[17];
    const float* g4 = (const float*)d_in[18], *be4 = (const float*)d_in[19];
    const float* w5 = (const float*)d_in[20], *b5 = (const float*)d_in[21];
    const float* g5 = (const float*)d_in[22], *be5 = (const float*)d_in[23];

    int R  = out_size / 512;   // output is [R, 512]
    int Np = in_sizes[1];      // number of points

    float* out = (float*)d_out;

    float *feat_p, *hA_p, *hB_p;
    cudaGetSymbolAddress((void**)&feat_p, g_feat);
    cudaGetSymbolAddress((void**)&hA_p,  g_hA);
    cudaGetSymbolAddress((void**)&hB_p,  g_hB);

    const int FPS_SMEM = PCAP * 4 * (int)sizeof(float);  // 64KB
    cudaFuncSetAttribute(fps_kernel, cudaFuncAttributeMaxDynamicSharedMemorySize, FPS_SMEM);

    // ---- grouping (privatized, no global atomics) ----
    int chunk = (Np + NB - 1) / NB;
    blockhist_kernel<<<NB, 512>>>(roi_idx, Np, chunk);
    totals_scan_kernel<<<1, 256>>>();
    blockbase_kernel<<<RMAX, 256>>>();
    scatter_kernel<<<NB, 512>>>(roi_idx, coords, Np, chunk);

    // ---- FPS + fused gather ----
    fps_kernel<<<R, 512, FPS_SMEM>>>(feats);

    // ---- MLP (3xTF32 tensor-core GEMMs) ----
    run_layer(feat_p, w1, b1, g1, be1, hA_p, R, KSEL * FDIM, 256, 8, 1);
    run_layer(hA_p,   w2, b2, g2, be2, hB_p, R, 256,          256, 4, 1);
    run_layer(hB_p,   w3, b3, g3, be3, hA_p, R, 256,          512, 4, 0);
    run_layer(hA_p,   w4, b4, g4, be4, hB_p, R, 512,          256, 4, 1);
    run_layer(hB_p,   w5, b5, g5, be5, out,  R, 256,          512, 4, 1);
}